// round 1
// baseline (speedup 1.0000x reference)
#include <cuda_runtime.h>
#include <math.h>

// RFFT via per-warp 512-point FFT.
// x: [32*4000, 512] fp32.  out: re [rows,257] then im [rows,257] concatenated.
// Decomposition: n = n1 + 16*n2  (n2 = lane in [0,32), n1 = register slot in [0,16))
//   X[k2 + 32*k1] = sum_{n1} W512^{n1 k2} W16^{n1 k1} * ( sum_{n2} x[n1+16 n2] W32^{n2 k2} )
// Step 1: 32-pt DIF FFT across lanes (shfl_xor), output k2 = bitrev5(lane)
// Step 2: twiddle W512^{n1*k2}
// Step 3: 16-pt DIF FFT in registers, output slot r holds k1 = bitrev4(r)
// Keep only k = k2 + 32*k1 <= 256.

#define WARPS_PER_BLOCK 8
#define THREADS_PER_BLOCK (WARPS_PER_BLOCK * 32)

__device__ float2 g_tw[512];   // g_tw[t] = exp(-2*pi*i*t/512)

__global__ void init_twiddles_kernel() {
    int t = threadIdx.x;
    if (t < 512) {
        double ang = -2.0 * 3.141592653589793238462643383279502884 * (double)t / 512.0;
        double s, c;
        sincos(ang, &s, &c);
        g_tw[t] = make_float2((float)c, (float)s);
    }
}

__global__ void __launch_bounds__(THREADS_PER_BLOCK)
rfft512_kernel(const float* __restrict__ x,
               float* __restrict__ out_re,
               float* __restrict__ out_im,
               int nrows)
{
    __shared__ float2 tw[512];
    for (int i = threadIdx.x; i < 512; i += THREADS_PER_BLOCK)
        tw[i] = g_tw[i];
    __syncthreads();

    const int lane = threadIdx.x & 31;
    const int warp = threadIdx.x >> 5;
    const int row  = blockIdx.x * WARPS_PER_BLOCK + warp;
    if (row >= nrows) return;

    // ---- load: slot n1 holds x[row, n1 + 16*lane] ----
    const float4* xv = (const float4*)(x + (size_t)row * 512 + 16 * lane);
    float re[16], im[16];
#pragma unroll
    for (int i = 0; i < 4; i++) {
        float4 v = xv[i];
        re[4*i+0] = v.x; re[4*i+1] = v.y; re[4*i+2] = v.z; re[4*i+3] = v.w;
    }

    // ---- step 1: 32-pt DIF FFT across lanes ----
    // stage m=16: imag is still zero everywhere -> halve the shuffles
    {
        const int m = 16;
        const int j = lane & (m - 1);
        const float2 w = tw[j * (256 / m)];       // W32^j
        const bool up = (lane & m) != 0;
#pragma unroll
        for (int s = 0; s < 16; s++) {
            float ar = __shfl_xor_sync(0xffffffffu, re[s], m);
            if (up) {
                float tr = ar - re[s];            // (a - b)
                re[s] = tr * w.x;
                im[s] = tr * w.y;
            } else {
                re[s] = re[s] + ar;
                im[s] = 0.0f;
            }
        }
    }
    // stages m = 8, 4, 2, 1
#pragma unroll
    for (int mi = 0; mi < 4; mi++) {
        const int m = 8 >> mi;
        const int j = lane & (m - 1);
        const float2 w = tw[j * (32 << mi)];      // W_{2m}^j = tw[j*256/m]
        const bool up = (lane & m) != 0;
#pragma unroll
        for (int s = 0; s < 16; s++) {
            float ar = __shfl_xor_sync(0xffffffffu, re[s], m);
            float ai = __shfl_xor_sync(0xffffffffu, im[s], m);
            if (up) {
                float tr = ar - re[s];
                float ti = ai - im[s];
                re[s] = tr * w.x - ti * w.y;
                im[s] = tr * w.y + ti * w.x;
            } else {
                re[s] += ar;
                im[s] += ai;
            }
        }
    }

    // lane now holds k2 = bitrev5(lane) for every slot
    const int k2 = __brev(lane) >> 27;

    // ---- step 2: twiddle by W512^{n1 * k2} (slot 0 twiddle = 1) ----
#pragma unroll
    for (int s = 1; s < 16; s++) {
        float2 w = tw[(s * k2) & 511];
        float tr = re[s] * w.x - im[s] * w.y;
        im[s]    = re[s] * w.y + im[s] * w.x;
        re[s]    = tr;
    }

    // ---- step 3: 16-pt DIF FFT in registers over n1 ----
#pragma unroll
    for (int mi = 0; mi < 4; mi++) {
        const int m = 8 >> mi;
#pragma unroll
        for (int g = 0; g < 16; g += 2 * m) {
#pragma unroll
            for (int j = 0; j < m; j++) {
                const float2 w = tw[j * (32 << mi)];  // W_{2m}^j
                const int p = g + j, q = g + j + m;
                float ar = re[p], ai = im[p];
                float br = re[q], bi = im[q];
                re[p] = ar + br;  im[p] = ai + bi;
                float tr = ar - br, ti = ai - bi;
                re[q] = tr * w.x - ti * w.y;
                im[q] = tr * w.y + ti * w.x;
            }
        }
    }

    // ---- store: slot r holds X[k2 + 32*bitrev4(r)], keep k <= 256 ----
    const size_t base = (size_t)row * 257;
#pragma unroll
    for (int r = 0; r < 16; r++) {
        const int k1 = __brev(r) >> 28;            // compile-time per unrolled r
        if (k1 < 8) {
            const int k = k2 + 32 * k1;
            out_re[base + k] = re[r];
            out_im[base + k] = im[r];
        } else if (k1 == 8) {                       // r == 1
            if (lane == 0) {                        // k2 == 0 -> k = 256
                out_re[base + 256] = re[r];
                out_im[base + 256] = im[r];
            }
        }
    }
}

extern "C" void kernel_launch(void* const* d_in, const int* in_sizes, int n_in,
                              void* d_out, int out_size)
{
    const float* x = (const float*)d_in[0];
    // d_in[1] (m_real) and d_in[2] (m_imag) are the fixed one-sided DFT matrices;
    // the FFT computes the identical projection, so they are not read.
    (void)n_in;

    const int nrows = in_sizes[0] / 512;            // 32*4000 = 128000
    float* out_re = (float*)d_out;
    float* out_im = out_re + (size_t)nrows * 257;
    (void)out_size;

    init_twiddles_kernel<<<1, 512>>>();

    const int blocks = (nrows + WARPS_PER_BLOCK - 1) / WARPS_PER_BLOCK;
    rfft512_kernel<<<blocks, THREADS_PER_BLOCK>>>(x, out_re, out_im, nrows);
}

// round 3
// speedup vs baseline: 2.0406x; 2.0406x over previous
#include <cuda_runtime.h>
#include <math.h>

// RFFT of x[128000, 512] via per-warp 512-pt complex FFT packing TWO real rows
// (z = xa + i*xb), unpacked by conjugate symmetry.
// Decomposition n = n1 + 16*n2: n2 = lane (0..31), n1 = register slot (0..15).
//  load:   coalesced LDG.128 -> XOR-swizzled smem stage -> aligned LDS.128
//  step 1: 32-pt DIF FFT across lanes (shfl_xor); lane then holds k2 = brev5(lane)
//  step 2: twiddle W512^{s*k2} via running complex product from w1 = W512^{k2}
//  step 3: 16-pt DIF FFT in registers (literal twiddles); slot r holds k1 = brev4(r)
//  unpack: Xa[k] = (Z[k]+conj(Z[512-k]))/2, Xb[k] = (Z[k]-conj(Z[512-k]))/(2i)
// out: re [rows,257] then im [rows,257] concatenated.

#define WARPS_PER_BLOCK 8
#define THREADS_PER_BLOCK (WARPS_PER_BLOCK * 32)

__global__ void __launch_bounds__(THREADS_PER_BLOCK, 4)
rfft512x2_kernel(const float* __restrict__ x,
                 float* __restrict__ out_re,
                 float* __restrict__ out_im,
                 int nrow_pairs)
{
    __shared__ float4 sbuf[WARPS_PER_BLOCK * 256];   // 32 KB: 256 16B-chunks/warp

    const int lane = threadIdx.x & 31;
    const int warp = threadIdx.x >> 5;
    const int rp   = blockIdx.x * WARPS_PER_BLOCK + warp;
    if (rp >= nrow_pairs) return;

    // ---- coalesced load + swizzled smem stage ----
    // chunks: row a = [0,128), row b = [128,256). swizzle: c ^ ((c>>3)&7)
    const float4* xv = (const float4*)(x + (size_t)(2 * rp) * 512);
    float4* sw = sbuf + warp * 256;
#pragma unroll
    for (int i = 0; i < 4; i++) {
        const int c  = 32 * i + lane;
        const int cs = c ^ ((c >> 3) & 7);
        sw[cs]       = xv[c];          // row a
        sw[128 + cs] = xv[128 + c];    // row b
    }
    __syncwarp();

    float re[16], im[16];
#pragma unroll
    for (int i = 0; i < 4; i++) {
        const int c  = 4 * lane + i;
        const int cs = c ^ ((c >> 3) & 7);
        float4 A = sw[cs];
        re[4*i+0] = A.x; re[4*i+1] = A.y; re[4*i+2] = A.z; re[4*i+3] = A.w;
        float4 B = sw[128 + cs];
        im[4*i+0] = B.x; im[4*i+1] = B.y; im[4*i+2] = B.z; im[4*i+3] = B.w;
    }

    // ---- step 1: 32-pt DIF FFT across lanes (twiddles via MUFU sincos) ----
#pragma unroll
    for (int mi = 0; mi < 5; mi++) {
        const int m = 16 >> mi;
        const int j = lane & (m - 1);
        float wr, wi;
        __sincosf(-3.14159265358979323846f * (float)j / (float)m, &wi, &wr);
        const bool up = (lane & m) != 0;
#pragma unroll
        for (int s = 0; s < 16; s++) {
            float ar = __shfl_xor_sync(0xffffffffu, re[s], m);
            float ai = __shfl_xor_sync(0xffffffffu, im[s], m);
            if (up) {
                float tr = ar - re[s];
                float ti = ai - im[s];
                re[s] = tr * wr - ti * wi;
                im[s] = tr * wi + ti * wr;
            } else {
                re[s] += ar;
                im[s] += ai;
            }
        }
    }

    const int k2 = __brev(lane) >> 27;   // lane holds Z-partials at freq k2 (mod 32)

    // ---- step 2: twiddle slot s by W512^{s*k2}, running product ----
    {
        float w1r, w1i;
        __sincosf(-3.14159265358979323846f * (float)k2 / 256.0f, &w1i, &w1r);
        float cr = w1r, ci = w1i;
        {   // s = 1
            float tr = re[1] * cr - im[1] * ci;
            im[1]    = re[1] * ci + im[1] * cr;
            re[1]    = tr;
        }
#pragma unroll
        for (int s = 2; s < 16; s++) {
            float nr = cr * w1r - ci * w1i;
            ci       = cr * w1i + ci * w1r;
            cr       = nr;
            float tr = re[s] * cr - im[s] * ci;
            im[s]    = re[s] * ci + im[s] * cr;
            re[s]    = tr;
        }
    }

    // ---- step 3: 16-pt DIF FFT in registers, literal twiddles ----
    const float W16r[8] = { 1.0f,  0.92387953251128674f,  0.70710678118654752f,
                            0.38268343236508977f, 0.0f, -0.38268343236508977f,
                           -0.70710678118654752f, -0.92387953251128674f };
    const float W16i[8] = { 0.0f, -0.38268343236508977f, -0.70710678118654752f,
                           -0.92387953251128674f, -1.0f, -0.92387953251128674f,
                           -0.70710678118654752f, -0.38268343236508977f };
#pragma unroll
    for (int mi = 0; mi < 4; mi++) {
        const int m = 8 >> mi;
#pragma unroll
        for (int g = 0; g < 16; g += 2 * m) {
#pragma unroll
            for (int j = 0; j < m; j++) {
                const float wr = W16r[j << mi];
                const float wi = W16i[j << mi];
                const int p = g + j, q = p + m;
                float ar = re[p], ai = im[p];
                float br = re[q], bi = im[q];
                re[p] = ar + br;  im[p] = ai + bi;
                float tr = ar - br, ti = ai - bi;
                re[q] = tr * wr - ti * wi;
                im[q] = tr * wi + ti * wr;
            }
        }
    }

    // ---- unpack two real spectra + store (each store: 32 lanes permute one 128B line) ----
    const int l2 = (lane == 0) ? 0 : (__brev(32 - k2) >> 27);  // partner lane
    const int P0tab[8] = {0, 3, 7, 5, 15, 13, 11, 9};          // lane-0 partner slot
    const size_t base_a = (size_t)(2 * rp) * 257;
    const size_t base_b = base_a + 257;

#pragma unroll
    for (int r = 0; r < 16; r += 2) {
        const int k1 = __brev(r) >> 28;          // compile-time, < 8 for even r
        const int k  = k2 + 32 * k1;
        float pr = __shfl_sync(0xffffffffu, re[15 - r], l2);
        float pi = __shfl_sync(0xffffffffu, im[15 - r], l2);
        if (lane == 0) { pr = re[P0tab[r >> 1]]; pi = im[P0tab[r >> 1]]; }
        const float zr = re[r], zi = im[r];
        out_re[base_a + k] = 0.5f * (zr + pr);
        out_im[base_a + k] = 0.5f * (zi - pi);
        out_re[base_b + k] = 0.5f * (zi + pi);
        out_im[base_b + k] = 0.5f * (pr - zr);
    }
    if (lane == 0) {   // k = 256 (slot r=1, self-partner at lane 0)
        out_re[base_a + 256] = re[1];
        out_im[base_a + 256] = 0.0f;
        out_re[base_b + 256] = im[1];
        out_im[base_b + 256] = 0.0f;
    }
}

extern "C" void kernel_launch(void* const* d_in, const int* in_sizes, int n_in,
                              void* d_out, int out_size)
{
    const float* x = (const float*)d_in[0];
    // d_in[1]/d_in[2] are the fixed one-sided DFT matrices; the FFT computes
    // the identical projection, so they are not read.
    (void)n_in; (void)out_size;

    const int nrows = in_sizes[0] / 512;         // 128000
    const int nrow_pairs = nrows / 2;            // 64000
    float* out_re = (float*)d_out;
    float* out_im = out_re + (size_t)nrows * 257;

    const int blocks = (nrow_pairs + WARPS_PER_BLOCK - 1) / WARPS_PER_BLOCK;
    rfft512x2_kernel<<<blocks, THREADS_PER_BLOCK>>>(x, out_re, out_im, nrow_pairs);
}